// round 15
// baseline (speedup 1.0000x reference)
#include <cuda_runtime.h>
#include <cuda_fp16.h>
#include <cuda_bf16.h>
#include <stdint.h>

// ============================================================================
// AWQ 4-bit linear: out[128,8192] = x[128,8192] @ dequant(W)^T + bias
// mma.sync.m16n8k16. B NEVER goes through SMEM as fp16: packed int4 words are
// cp.async'd (4KB/chunk), read back with broadcast LDS.128, and dequantized
// IN REGISTERS directly into mma B-fragments (lop3+hsub2+hmul2 per reg).
// The lop3 nibble trick yields k-pairs (t,t+4); the x scratch buffer is
// written k-PERMUTED the same way during dtype conversion, so the contraction
// is exact. Zero/scale pairs precomputed to a half2(1024+z, s) table.
// CTA: 256 thr, 8 warps, grid 4(M)x2(N), warp tile 32x32. N_TILE=64 -> 128
// CTAs. 3-stage ring (A fp16 34KB + B packed 5KB per stage), 1 barrier/chunk.
// ============================================================================

#define THREADS   256
#define N_TILE    64
#define K_DIM     8192
#define QW_COLS   1024
#define NCHUNK    64
#define A_ROW     272                 // 256B data + 16B pad
#define A_STAGE   (128 * A_ROW)       // 34816
#define B_ROW     80                  // 64B packed data + 16B pad (16B-aligned, conflict-free)
#define B_STAGE   (64 * B_ROW)        // 5120
#define STAGE_SZ  (A_STAGE + B_STAGE) // 39936
#define NSTAGE    3
#define SMEM_TOTAL (NSTAGE * STAGE_SZ)  // 119808

#define X_ELEMS      1048576
#define SCALE_ELEMS  524288

__device__ __half   g_x[X_ELEMS];        // k-permuted: 8-group stored as (t, t+4) pairs
__device__ __half   g_scales[SCALE_ELEMS];
__device__ uint32_t g_zs[SCALE_ELEMS];   // half2(1024+z, s) per (n, group)
__device__ int      g_dtype;             // 0 fp32, 1 fp16, 2 bf16 storage

// ---------------------------------------------------------------------------
// dtype detection from scales (values in (0.001, 0.02))
// ---------------------------------------------------------------------------
__global__ void detect_dtype_kernel(const uint32_t* __restrict__ scales_raw) {
    const int lane = threadIdx.x;
    int cntHi = 0, cntLo = 0;
#pragma unroll
    for (int i = 0; i < 8; i++) {
        const uint32_t w = scales_raw[lane * 8 + i];
        const uint32_t eHi = (w >> 23) & 0xFF;
        const uint32_t eLo = (w >> 7) & 0xFF;
        cntHi += (eHi >= 110 && eHi <= 126);
        cntLo += (eLo >= 110 && eLo <= 126);
    }
#pragma unroll
    for (int off = 16; off > 0; off >>= 1) {
        cntHi += __shfl_xor_sync(0xFFFFFFFF, cntHi, off);
        cntLo += __shfl_xor_sync(0xFFFFFFFF, cntLo, off);
    }
    if (lane == 0) g_dtype = (cntHi > 192) ? ((cntLo > 192) ? 2 : 0) : 1;
}

// Plain conversion (no permutation) — used for scales.
__global__ void convert_kernel(const void* __restrict__ src, __half* __restrict__ dst, int n) {
    const int dt = g_dtype;
    const int stride = gridDim.x * blockDim.x;
    int i = blockIdx.x * blockDim.x + threadIdx.x;
    if (dt == 0) {
        const float4* s4 = (const float4*)src;
        for (; i < n / 4; i += stride) {
            const float4 v = s4[i];
            __half2 lo = __floats2half2_rn(v.x, v.y);
            __half2 hi = __floats2half2_rn(v.z, v.w);
            uint2 o;
            o.x = *reinterpret_cast<uint32_t*>(&lo);
            o.y = *reinterpret_cast<uint32_t*>(&hi);
            *reinterpret_cast<uint2*>(dst + i * 4) = o;
        }
    } else if (dt == 2) {
        const __nv_bfloat162* s2 = (const __nv_bfloat162*)src;
        for (; i < n / 4; i += stride) {
            const __nv_bfloat162 a = s2[i * 2], b = s2[i * 2 + 1];
            __half2 lo = __floats2half2_rn(__bfloat162float(a.x), __bfloat162float(a.y));
            __half2 hi = __floats2half2_rn(__bfloat162float(b.x), __bfloat162float(b.y));
            uint2 o;
            o.x = *reinterpret_cast<uint32_t*>(&lo);
            o.y = *reinterpret_cast<uint32_t*>(&hi);
            *reinterpret_cast<uint2*>(dst + i * 4) = o;
        }
    } else {
        const uint2* s2 = (const uint2*)src;
        for (; i < n / 4; i += stride)
            *reinterpret_cast<uint2*>(dst + i * 4) = s2[i];
    }
}

// x conversion WITH k-permutation: each 8-group stored as pairs (t, t+4),
// matching the lop3 nibble-extraction order of packed qweight words.
__global__ void convert_x_kernel(const void* __restrict__ src, __half* __restrict__ dst) {
    const int dt = g_dtype;
    const int g = blockIdx.x * blockDim.x + threadIdx.x;   // 8-element group
    if (g >= X_ELEMS / 8) return;
    uint4 o;
    if (dt == 0) {
        const float4* s4 = (const float4*)src;
        const float4 a = s4[g * 2], b = s4[g * 2 + 1];     // f0..f3, f4..f7
        __half2 h0 = __floats2half2_rn(a.x, b.x);          // (f0, f4)
        __half2 h1 = __floats2half2_rn(a.y, b.y);          // (f1, f5)
        __half2 h2 = __floats2half2_rn(a.z, b.z);          // (f2, f6)
        __half2 h3 = __floats2half2_rn(a.w, b.w);          // (f3, f7)
        o.x = *reinterpret_cast<uint32_t*>(&h0);
        o.y = *reinterpret_cast<uint32_t*>(&h1);
        o.z = *reinterpret_cast<uint32_t*>(&h2);
        o.w = *reinterpret_cast<uint32_t*>(&h3);
    } else if (dt == 2) {
        const __nv_bfloat16* sb = (const __nv_bfloat16*)src + g * 8;
        float f[8];
#pragma unroll
        for (int t = 0; t < 8; t++) f[t] = __bfloat162float(sb[t]);
        __half2 h0 = __floats2half2_rn(f[0], f[4]);
        __half2 h1 = __floats2half2_rn(f[1], f[5]);
        __half2 h2 = __floats2half2_rn(f[2], f[6]);
        __half2 h3 = __floats2half2_rn(f[3], f[7]);
        o.x = *reinterpret_cast<uint32_t*>(&h0);
        o.y = *reinterpret_cast<uint32_t*>(&h1);
        o.z = *reinterpret_cast<uint32_t*>(&h2);
        o.w = *reinterpret_cast<uint32_t*>(&h3);
    } else {
        const uint4 v = reinterpret_cast<const uint4*>(src)[g];  // h0h1,h2h3,h4h5,h6h7
        o.x = __byte_perm(v.x, v.z, 0x5410);   // (h0,h4)
        o.y = __byte_perm(v.x, v.z, 0x7632);   // (h1,h5)
        o.z = __byte_perm(v.y, v.w, 0x5410);   // (h2,h6)
        o.w = __byte_perm(v.y, v.w, 0x7632);   // (h3,h7)
    }
    reinterpret_cast<uint4*>(dst)[g] = o;
}

// Precompute half2(1024+z, s) per (n, group).
__global__ void build_zs_kernel(const int* __restrict__ qzeros) {
    const int idx = blockIdx.x * blockDim.x + threadIdx.x;
    if (idx >= SCALE_ELEMS) return;
    const int n = idx >> 6, g = idx & 63;
    const int z = (qzeros[n * 8 + (g >> 3)] >> ((g & 7) * 4)) & 15;
    const __half zp = __float2half_rn(1024.0f + (float)z);
    const __half s = g_scales[idx];
    const __half2 pack = __halves2half2(zp, s);
    g_zs[idx] = *reinterpret_cast<const uint32_t*>(&pack);
}

// ---------------------------------------------------------------------------
// GEMM helpers
// ---------------------------------------------------------------------------
static __device__ __forceinline__ uint32_t smem_u32(const void* p) {
    uint32_t r;
    asm("{ .reg .u64 t; cvta.to.shared.u64 t, %1; cvt.u32.u64 %0, t; }" : "=r"(r) : "l"(p));
    return r;
}
static __device__ __forceinline__ uint32_t h2u(__half2 h) {
    return *reinterpret_cast<uint32_t*>(&h);
}
static __device__ __forceinline__ void cp_async16(uint32_t dst, const void* src) {
    asm volatile("cp.async.cg.shared.global [%0], [%1], 16;" :: "r"(dst), "l"(src) : "memory");
}
static __device__ __forceinline__ void cp_commit() {
    asm volatile("cp.async.commit_group;" ::: "memory");
}
template <int N>
static __device__ __forceinline__ void cp_wait() {
    asm volatile("cp.async.wait_group %0;" :: "n"(N) : "memory");
}
static __device__ __forceinline__ void ldsm_x4(uint32_t* r, uint32_t addr) {
    asm volatile("ldmatrix.sync.aligned.m8n8.x4.shared.b16 {%0,%1,%2,%3}, [%4];"
                 : "=r"(r[0]), "=r"(r[1]), "=r"(r[2]), "=r"(r[3]) : "r"(addr));
}
static __device__ __forceinline__ uint4 lds128(uint32_t addr) {
    uint4 r;
    asm volatile("ld.shared.v4.u32 {%0,%1,%2,%3}, [%4];"
                 : "=r"(r.x), "=r"(r.y), "=r"(r.z), "=r"(r.w) : "r"(addr));
    return r;
}
static __device__ __forceinline__ void mma16816(float* d, const uint32_t* a, const uint32_t* b) {
    asm volatile("mma.sync.aligned.m16n8k16.row.col.f32.f16.f16.f32 "
                 "{%0,%1,%2,%3}, {%4,%5,%6,%7}, {%8,%9}, {%0,%1,%2,%3};"
                 : "+f"(d[0]), "+f"(d[1]), "+f"(d[2]), "+f"(d[3])
                 : "r"(a[0]), "r"(a[1]), "r"(a[2]), "r"(a[3]), "r"(b[0]), "r"(b[1]));
}
// One b-fragment register from a (pre-shifted) packed word: nibbles (t, t+4)
// -> half2, exact (v - (1024+z)) then single-rounded * s.
static __device__ __forceinline__ uint32_t dqreg(uint32_t v, __half2 zp2, __half2 s2) {
    uint32_t h;
    asm("lop3.b32 %0, %1, 0x000F000F, 0x64006400, 0xEA;" : "=r"(h) : "r"(v));
    return h2u(__hmul2(__hsub2(*reinterpret_cast<__half2*>(&h), zp2), s2));
}

extern __shared__ char dyn_smem[];

__global__ void __launch_bounds__(THREADS, 1)
awq_kernel(const int* __restrict__ qweight, const float* __restrict__ bias,
           float* __restrict__ out)
{
    const __half* x = g_x;
    const uint32_t sb = smem_u32(dyn_smem);
    const int tid = threadIdx.x;
    const int wid = tid >> 5;
    const int lid = tid & 31;
    const int n0 = blockIdx.x * N_TILE;

    // ---- A fill: 2048 16B-slots (128 rows x 16 units), 8 per thread ----
    uint32_t a_dst_off[8], a_src_off[8];
#pragma unroll
    for (int it = 0; it < 8; it++) {
        const int j = tid + THREADS * it;
        const int row = j >> 4, u = j & 15;
        a_dst_off[it] = (uint32_t)(row * A_ROW + u * 16);
        a_src_off[it] = (uint32_t)(row * K_DIM + u * 8);
    }
    // ---- B fill: 256 16B-slots (64 rows x 4 units), 1 per thread ----
    const uint32_t b_dst_off = (uint32_t)((tid >> 2) * B_ROW + (tid & 3) * 16);
    const int* b_src = qweight + (size_t)(n0 + (tid >> 2)) * QW_COLS + (tid & 3) * 4;

    // ---- compute-side: warp grid 4(M) x 2(N), warp tile 32x32 ----
    const int warp_m = wid >> 1;                 // 0..3
    const int warp_n = wid & 1;                  // 0..1
    uint32_t rowA_off[2];
#pragma unroll
    for (int mt = 0; mt < 2; mt++)
        rowA_off[mt] = (uint32_t)((warp_m * 32 + mt * 16 + (lid & 15)) * A_ROW
                                  + ((lid >> 4) & 1) * 16);
    const int sh = (lid & 3) * 4;                // nibble shift for this lane
    const int nrow_l = warp_n * 32 + (lid >> 2); // local B row (+ nt*8)
    uint32_t bOff[4];
    const uint32_t* zs_ptr[4];
#pragma unroll
    for (int nt = 0; nt < 4; nt++) {
        bOff[nt] = (uint32_t)((nrow_l + nt * 8) * B_ROW);
        zs_ptr[nt] = g_zs + (size_t)(n0 + nrow_l + nt * 8) * 64;
    }

    float acc[2][4][4];
#pragma unroll
    for (int mt = 0; mt < 2; mt++)
#pragma unroll
        for (int nt = 0; nt < 4; nt++)
#pragma unroll
            for (int e = 0; e < 4; e++) acc[mt][nt][e] = 0.0f;

    uint32_t zs_cur[4], zs_nxt[4];

    auto fill = [&](int i, int stage) {
        const uint32_t as = sb + stage * STAGE_SZ;
        const __half* xp = x + i * 128;
#pragma unroll
        for (int it = 0; it < 8; it++)
            cp_async16(as + a_dst_off[it], xp + a_src_off[it]);
        cp_async16(as + A_STAGE + b_dst_off, b_src + i * 16);
        cp_commit();
    };
    auto compute = [&](int stage) {
        const uint32_t ab = sb + stage * STAGE_SZ;
        const uint32_t bb = ab + A_STAGE;
        __half2 zp2[4], s2[4];
#pragma unroll
        for (int nt = 0; nt < 4; nt++) {
            const __half2 zs = *reinterpret_cast<const __half2*>(&zs_cur[nt]);
            zp2[nt] = __half2half2(__low2half(zs));
            s2[nt]  = __half2half2(__high2half(zs));
        }
        uint4 wq[4], wqn[4];
#pragma unroll
        for (int nt = 0; nt < 4; nt++) wq[nt] = lds128(bb + bOff[nt]);
#pragma unroll
        for (int p = 0; p < 4; p++) {
            if (p < 3) {
#pragma unroll
                for (int nt = 0; nt < 4; nt++)
                    wqn[nt] = lds128(bb + bOff[nt] + (p + 1) * 16);
            }
#pragma unroll
            for (int e = 0; e < 2; e++) {
                const int s = 2 * p + e;
                uint32_t af0[4], af1[4];
                ldsm_x4(af0, ab + rowA_off[0] + 32 * s);
                ldsm_x4(af1, ab + rowA_off[1] + 32 * s);
#pragma unroll
                for (int nt = 0; nt < 4; nt++) {
                    const uint32_t w0 = e ? wq[nt].z : wq[nt].x;
                    const uint32_t w1 = e ? wq[nt].w : wq[nt].y;
                    uint32_t bf[2];
                    bf[0] = dqreg(w0 >> sh, zp2[nt], s2[nt]);
                    bf[1] = dqreg(w1 >> sh, zp2[nt], s2[nt]);
                    mma16816(acc[0][nt], af0, bf);
                    mma16816(acc[1][nt], af1, bf);
                }
            }
#pragma unroll
            for (int nt = 0; nt < 4; nt++) wq[nt] = wqn[nt];
        }
    };

    // ---- prologue ----
    fill(0, 0);
    fill(1, 1);
#pragma unroll
    for (int nt = 0; nt < 4; nt++) zs_cur[nt] = zs_ptr[nt][0];

    // ---- mainloop: ONE barrier per chunk ----
#pragma unroll 1
    for (int i = 0; i < NCHUNK; i++) {
        if (i + 1 < NCHUNK) cp_wait<1>(); else cp_wait<0>();
        __syncthreads();                 // A(i)+B(i) visible; stage (i+2)%3 free
        if (i + 2 < NCHUNK) fill(i + 2, (i + 2) % 3);
        if (i + 1 < NCHUNK) {
#pragma unroll
            for (int nt = 0; nt < 4; nt++) zs_nxt[nt] = zs_ptr[nt][i + 1];
        }
        compute(i % 3);
#pragma unroll
        for (int nt = 0; nt < 4; nt++) zs_cur[nt] = zs_nxt[nt];
    }

    // ---- epilogue: fp16 round (match fp16 einsum), + fp32 bias ----
    const int r0 = lid >> 2;
    const int c0 = (lid & 3) * 2;
#pragma unroll
    for (int mt = 0; mt < 2; mt++) {
#pragma unroll
        for (int nt = 0; nt < 4; nt++) {
            const int n = n0 + warp_n * 32 + nt * 8 + c0;
            const float bx = bias[n], by = bias[n + 1];
            const int m = warp_m * 32 + mt * 16 + r0;
            float2 o0, o1;
            o0.x = __half2float(__float2half_rn(acc[mt][nt][0])) + bx;
            o0.y = __half2float(__float2half_rn(acc[mt][nt][1])) + by;
            o1.x = __half2float(__float2half_rn(acc[mt][nt][2])) + bx;
            o1.y = __half2float(__float2half_rn(acc[mt][nt][3])) + by;
            *reinterpret_cast<float2*>(out + (size_t)m * 8192 + n) = o0;
            *reinterpret_cast<float2*>(out + (size_t)(m + 8) * 8192 + n) = o1;
        }
    }
}

// ===========================================================================
// Host: bind inputs BY ELEMENT COUNT (all distinct) — immune to ordering.
//   x 1048576 | qweight 8388608 | scales 524288 | qzeros 65536 | bias 8192
// ===========================================================================
extern "C" void kernel_launch(void* const* d_in, const int* in_sizes, int n_in,
                              void* d_out, int out_size) {
    const void* x_raw = nullptr;
    const int* qweight = nullptr;
    const void* scales_raw = nullptr;
    const int* qzeros = nullptr;
    const float* bias = nullptr;

    for (int i = 0; i < n_in; i++) {
        switch (in_sizes[i]) {
            case X_ELEMS:     x_raw      = d_in[i];               break;
            case 8388608:     qweight    = (const int*)d_in[i];   break;
            case SCALE_ELEMS: scales_raw = d_in[i];               break;
            case 65536:       qzeros     = (const int*)d_in[i];   break;
            case 8192:        bias       = (const float*)d_in[i]; break;
            default: break;
        }
    }

    float* out = (float*)d_out;

    __half* gx = nullptr;
    __half* gs = nullptr;
    cudaGetSymbolAddress((void**)&gx, g_x);
    cudaGetSymbolAddress((void**)&gs, g_scales);

    detect_dtype_kernel<<<1, 32>>>((const uint32_t*)scales_raw);
    convert_x_kernel<<<(X_ELEMS / 8 + 255) / 256, 256>>>(x_raw, gx);
    convert_kernel<<<64, 256>>>(scales_raw, gs, SCALE_ELEMS);
    build_zs_kernel<<<SCALE_ELEMS / 256, 256>>>(qzeros);

    cudaFuncSetAttribute(awq_kernel, cudaFuncAttributeMaxDynamicSharedMemorySize, SMEM_TOTAL);
    awq_kernel<<<8192 / N_TILE, THREADS, SMEM_TOTAL>>>(qweight, bias, out);
}

// round 16
// speedup vs baseline: 1.7495x; 1.7495x over previous
#include <cuda_runtime.h>
#include <cuda_fp16.h>
#include <cuda_bf16.h>
#include <stdint.h>

// ============================================================================
// AWQ 4-bit linear: out[128,8192] = x[128,8192] @ dequant(W)^T + bias
// mma.sync.m16n8k16, 3-stage SMEM ring, ONE barrier per K-chunk, and
// FRAGMENT REGISTER DOUBLE-BUFFERING: k-step w+1's ldmatrix ops issue before
// k-step w's mma group, hiding LDSM latency behind tensor work (r10-r15
// showed ~18cyc/mma stall from ldsm-immediately-before-mma ordering).
// CTA: 256 threads (8 warps, 4(M) x 2(N)), N_TILE=64 -> 128 CTAs.
// K chunk = 128 = one quant group. Padded SMEM rows (272B), conflict-free.
// fp16-origin inputs (x, scales) arrive promoted; dtype detected from scales'
// exponent stats, converted once to fp16 scratch.
// ============================================================================

#define THREADS   256
#define N_TILE    64
#define K_DIM     8192
#define QW_COLS   1024
#define NCHUNK    64
#define ROW_BYTES 272            // 256B data + 16B pad (conflict-free)

#define A_STAGE   (128 * ROW_BYTES)   // 34816
#define B_STAGE   (64 * ROW_BYTES)    // 17408
#define STAGE_SZ  (A_STAGE + B_STAGE) // 52224
#define NSTAGE    3
#define SMEM_TOTAL (NSTAGE * STAGE_SZ)  // 156672 bytes

#define X_ELEMS      1048576
#define SCALE_ELEMS  524288

__device__ __half g_x[X_ELEMS];
__device__ __half g_scales[SCALE_ELEMS];
__device__ int    g_dtype;   // 0 = fp32 storage, 1 = fp16 storage, 2 = bf16

// ---------------------------------------------------------------------------
// dtype detection from scales (values in (0.001, 0.02))
// ---------------------------------------------------------------------------
__global__ void detect_dtype_kernel(const uint32_t* __restrict__ scales_raw) {
    const int lane = threadIdx.x;
    int cntHi = 0, cntLo = 0;
#pragma unroll
    for (int i = 0; i < 8; i++) {
        const uint32_t w = scales_raw[lane * 8 + i];
        const uint32_t eHi = (w >> 23) & 0xFF;
        const uint32_t eLo = (w >> 7) & 0xFF;
        cntHi += (eHi >= 110 && eHi <= 126);
        cntLo += (eLo >= 110 && eLo <= 126);
    }
#pragma unroll
    for (int off = 16; off > 0; off >>= 1) {
        cntHi += __shfl_xor_sync(0xFFFFFFFF, cntHi, off);
        cntLo += __shfl_xor_sync(0xFFFFFFFF, cntLo, off);
    }
    if (lane == 0) g_dtype = (cntHi > 192) ? ((cntLo > 192) ? 2 : 0) : 1;
}

__global__ void convert_kernel(const void* __restrict__ src, __half* __restrict__ dst, int n) {
    const int dt = g_dtype;
    const int stride = gridDim.x * blockDim.x;
    int i = blockIdx.x * blockDim.x + threadIdx.x;
    if (dt == 0) {
        const float4* s4 = (const float4*)src;
        for (; i < n / 4; i += stride) {
            const float4 v = s4[i];
            __half2 lo = __floats2half2_rn(v.x, v.y);
            __half2 hi = __floats2half2_rn(v.z, v.w);
            uint2 o;
            o.x = *reinterpret_cast<uint32_t*>(&lo);
            o.y = *reinterpret_cast<uint32_t*>(&hi);
            *reinterpret_cast<uint2*>(dst + i * 4) = o;
        }
    } else if (dt == 2) {
        const __nv_bfloat162* s2 = (const __nv_bfloat162*)src;
        for (; i < n / 4; i += stride) {
            const __nv_bfloat162 a = s2[i * 2], b = s2[i * 2 + 1];
            __half2 lo = __floats2half2_rn(__bfloat162float(a.x), __bfloat162float(a.y));
            __half2 hi = __floats2half2_rn(__bfloat162float(b.x), __bfloat162float(b.y));
            uint2 o;
            o.x = *reinterpret_cast<uint32_t*>(&lo);
            o.y = *reinterpret_cast<uint32_t*>(&hi);
            *reinterpret_cast<uint2*>(dst + i * 4) = o;
        }
    } else {
        const uint2* s2 = (const uint2*)src;
        for (; i < n / 4; i += stride)
            *reinterpret_cast<uint2*>(dst + i * 4) = s2[i];
    }
}

// ---------------------------------------------------------------------------
// GEMM helpers
// ---------------------------------------------------------------------------
static __device__ __forceinline__ uint32_t smem_u32(const void* p) {
    uint32_t r;
    asm("{ .reg .u64 t; cvta.to.shared.u64 t, %1; cvt.u32.u64 %0, t; }" : "=r"(r) : "l"(p));
    return r;
}
static __device__ __forceinline__ uint32_t h2u(__half2 h) {
    return *reinterpret_cast<uint32_t*>(&h);
}
static __device__ __forceinline__ void cp_async16(uint32_t dst, const void* src) {
    asm volatile("cp.async.cg.shared.global [%0], [%1], 16;" :: "r"(dst), "l"(src) : "memory");
}
static __device__ __forceinline__ void cp_commit() {
    asm volatile("cp.async.commit_group;" ::: "memory");
}
template <int N>
static __device__ __forceinline__ void cp_wait() {
    asm volatile("cp.async.wait_group %0;" :: "n"(N) : "memory");
}
static __device__ __forceinline__ void ldsm_x4(uint32_t* r, uint32_t addr) {
    asm volatile("ldmatrix.sync.aligned.m8n8.x4.shared.b16 {%0,%1,%2,%3}, [%4];"
                 : "=r"(r[0]), "=r"(r[1]), "=r"(r[2]), "=r"(r[3]) : "r"(addr));
}
static __device__ __forceinline__ void mma16816(float* d, const uint32_t* a, const uint32_t* b) {
    asm volatile("mma.sync.aligned.m16n8k16.row.col.f32.f16.f16.f32 "
                 "{%0,%1,%2,%3}, {%4,%5,%6,%7}, {%8,%9}, {%0,%1,%2,%3};"
                 : "+f"(d[0]), "+f"(d[1]), "+f"(d[2]), "+f"(d[3])
                 : "r"(a[0]), "r"(a[1]), "r"(a[2]), "r"(a[3]), "r"(b[0]), "r"(b[1]));
}

// Dequant one packed int32 (8 nibbles n0..n7) -> 8 fp16 in LOGICAL order.
static __device__ __forceinline__ void dq_sts(uint32_t q, __half2 zp, __half2 s, uint32_t addr) {
    uint32_t h0, h1, h2, h3;
    asm("lop3.b32 %0, %1, 0x000F000F, 0x64006400, 0xEA;" : "=r"(h0) : "r"(q));        // (n0,n4)
    asm("lop3.b32 %0, %1, 0x000F000F, 0x64006400, 0xEA;" : "=r"(h1) : "r"(q >> 4));   // (n1,n5)
    asm("lop3.b32 %0, %1, 0x000F000F, 0x64006400, 0xEA;" : "=r"(h2) : "r"(q >> 8));   // (n2,n6)
    asm("lop3.b32 %0, %1, 0x000F000F, 0x64006400, 0xEA;" : "=r"(h3) : "r"(q >> 12));  // (n3,n7)
    uint32_t w0 = h2u(__hmul2(__hsub2(*reinterpret_cast<__half2*>(&h0), zp), s));
    uint32_t w1 = h2u(__hmul2(__hsub2(*reinterpret_cast<__half2*>(&h1), zp), s));
    uint32_t w2 = h2u(__hmul2(__hsub2(*reinterpret_cast<__half2*>(&h2), zp), s));
    uint32_t w3 = h2u(__hmul2(__hsub2(*reinterpret_cast<__half2*>(&h3), zp), s));
    uint32_t l0 = __byte_perm(w0, w1, 0x5410);  // (n0,n1)
    uint32_t l1 = __byte_perm(w2, w3, 0x5410);  // (n2,n3)
    uint32_t l2 = __byte_perm(w0, w1, 0x7632);  // (n4,n5)
    uint32_t l3 = __byte_perm(w2, w3, 0x7632);  // (n6,n7)
    asm volatile("st.shared.v4.b32 [%0], {%1,%2,%3,%4};"
                 :: "r"(addr), "r"(l0), "r"(l1), "r"(l2), "r"(l3) : "memory");
}

struct BRegs {
    uint32_t w[4];
    __half sA, sB;
    int zwA, zwB;
};

extern __shared__ char dyn_smem[];

__global__ void __launch_bounds__(THREADS, 1)
awq_kernel(const int* __restrict__ qweight, const int* __restrict__ qzeros,
           const float* __restrict__ bias, float* __restrict__ out)
{
    const __half* x = g_x;
    const __half* scales = g_scales;
    const uint32_t sb = smem_u32(dyn_smem);
    const int tid = threadIdx.x;
    const int wid = tid >> 5;
    const int lid = tid & 31;
    const int n0 = blockIdx.x * N_TILE;

    // ---- A fill mapping: 2048 16B-slots over 256 threads x 8 iters ----
    uint32_t a_dst_off[8], a_src_off[8];
#pragma unroll
    for (int it = 0; it < 8; it++) {
        const int j = tid + THREADS * it;
        const int row = j >> 4, u = j & 15;
        a_dst_off[it] = (uint32_t)(row * ROW_BYTES + u * 16);
        a_src_off[it] = (uint32_t)(row * K_DIM + u * 8);
    }
    // ---- B dequant mapping: thread -> rows {bg, bg+32}, k-units {bl, bl+8} ----
    const int bl = tid & 7, bg = tid >> 3;
    const uint32_t b_off0 = (uint32_t)(bg * ROW_BYTES + bl * 16);
    const uint32_t b_off1 = (uint32_t)((bg + 32) * ROW_BYTES + bl * 16);
    const int* qb0 = qweight + (n0 + bg) * QW_COLS + bl;
    const __half* sRowA = scales + (n0 + bg) * 64;
    const __half* sRowB = scales + (n0 + bg + 32) * 64;
    const int* zRowA = qzeros + (n0 + bg) * 8;
    const int* zRowB = qzeros + (n0 + bg + 32) * 8;

    // ---- compute-side addressing: warp grid 4(M) x 2(N) ----
    const int warp_m = wid >> 1;                  // 0..3 -> rows [warp_m*32, +32)
    const int warp_n = wid & 1;                   // 0..1 -> cols [warp_n*32, +32)
    const int lrowA = lid & 15;
    const int kblkA = (lid >> 4) & 1;
    uint32_t rowA_off[2];
#pragma unroll
    for (int mt = 0; mt < 2; mt++)
        rowA_off[mt] = (uint32_t)((warp_m * 32 + mt * 16 + lrowA) * ROW_BYTES + kblkA * 16);
    const int gB = lid >> 3, rB = lid & 7;
    uint32_t bB_off[2];
#pragma unroll
    for (int pair = 0; pair < 2; pair++)
        bB_off[pair] = (uint32_t)((warp_n * 32 + pair * 16 + (gB >> 1) * 8 + rB) * ROW_BYTES
                                  + (gB & 1) * 16);

    float acc[2][4][4];
#pragma unroll
    for (int mt = 0; mt < 2; mt++)
#pragma unroll
        for (int nt = 0; nt < 4; nt++)
#pragma unroll
            for (int e = 0; e < 4; e++) acc[mt][nt][e] = 0.0f;

    auto fill_A = [&](int i, int stage) {
        const uint32_t as = sb + stage * STAGE_SZ;
        const __half* xp = x + i * 128;
#pragma unroll
        for (int it = 0; it < 8; it++)
            cp_async16(as + a_dst_off[it], xp + a_src_off[it]);
        cp_commit();
    };
    auto load_B = [&](int i, BRegs& r) {
        const int* qb = qb0 + i * 16;
        r.w[0] = (uint32_t)qb[0];
        r.w[1] = (uint32_t)qb[32 * QW_COLS];
        r.w[2] = (uint32_t)qb[8];
        r.w[3] = (uint32_t)qb[32 * QW_COLS + 8];
        r.sA = sRowA[i];
        r.sB = sRowB[i];
        r.zwA = zRowA[i >> 3];
        r.zwB = zRowB[i >> 3];
    };
    auto store_B = [&](int i, int stage, const BRegs& r) {
        const uint32_t bb = sb + stage * STAGE_SZ + A_STAGE;
        const int zA = (r.zwA >> ((i & 7) * 4)) & 15;
        const int zB = (r.zwB >> ((i & 7) * 4)) & 15;
        const __half2 zpA = __float2half2_rn(1024.0f + (float)zA);
        const __half2 zpB = __float2half2_rn(1024.0f + (float)zB);
        const __half2 s2A = __half2half2(r.sA);
        const __half2 s2B = __half2half2(r.sB);
        dq_sts(r.w[0], zpA, s2A, bb + b_off0);
        dq_sts(r.w[1], zpB, s2B, bb + b_off1);
        dq_sts(r.w[2], zpA, s2A, bb + b_off0 + 128);
        dq_sts(r.w[3], zpB, s2B, bb + b_off1 + 128);
    };

    // ---- prologue: chunks 0,1 into stages 0,1; regs for chunk 2 ----
    fill_A(0, 0);
    fill_A(1, 1);
    BRegs rcur, rnext;
    load_B(0, rcur);
    load_B(1, rnext);
    store_B(0, 0, rcur);
    store_B(1, 1, rnext);
    load_B(2, rcur);                 // rcur holds chunk 2 data for iter 0

    // ---- mainloop: ONE barrier per chunk; fragment double-buffering ----
#pragma unroll 1
    for (int i = 0; i < NCHUNK; i++) {
        if (i + 2 < NCHUNK) cp_wait<1>(); else cp_wait<0>();
        __syncthreads();             // A(i)+B(i) visible; stage (i+2)%3 free

        const uint32_t ab = sb + (i % 3) * STAGE_SZ;
        const uint32_t bb = ab + A_STAGE;

        // Prime k-step 0 fragments FIRST (head of L1tex queue).
        uint32_t af[2][2][4], bf[2][2][4];
        ldsm_x4(af[0][0], ab + rowA_off[0]);
        ldsm_x4(af[0][1], ab + rowA_off[1]);
        ldsm_x4(bf[0][0], bb + bB_off[0]);
        ldsm_x4(bf[0][1], bb + bB_off[1]);

        // Overlap LDSM latency with next-chunk staging work.
        if (i + 3 < NCHUNK) load_B(i + 3, rnext);
        if (i + 2 < NCHUNK) {
            store_B(i + 2, (i + 2) % 3, rcur);
            fill_A(i + 2, (i + 2) % 3);
        }

#pragma unroll
        for (int w = 0; w < 8; w++) {
            const int cur = w & 1, nxt = cur ^ 1;
            if (w < 7) {
                ldsm_x4(af[nxt][0], ab + rowA_off[0] + 32 * (w + 1));
                ldsm_x4(af[nxt][1], ab + rowA_off[1] + 32 * (w + 1));
                ldsm_x4(bf[nxt][0], bb + bB_off[0] + 32 * (w + 1));
                ldsm_x4(bf[nxt][1], bb + bB_off[1] + 32 * (w + 1));
            }
#pragma unroll
            for (int mt = 0; mt < 2; mt++) {
                mma16816(acc[mt][0], af[cur][mt], bf[cur][0] + 0);
                mma16816(acc[mt][1], af[cur][mt], bf[cur][0] + 2);
                mma16816(acc[mt][2], af[cur][mt], bf[cur][1] + 0);
                mma16816(acc[mt][3], af[cur][mt], bf[cur][1] + 2);
            }
        }
        rcur = rnext;
    }

    // ---- epilogue: fp16 round (match fp16 einsum), + fp32 bias ----
    const int r0 = lid >> 2;
    const int c0 = (lid & 3) * 2;
#pragma unroll
    for (int mt = 0; mt < 2; mt++) {
#pragma unroll
        for (int nt = 0; nt < 4; nt++) {
            const int n = n0 + warp_n * 32 + nt * 8 + c0;
            const float bx = bias[n], by = bias[n + 1];
            const int m = warp_m * 32 + mt * 16 + r0;
            float2 o0, o1;
            o0.x = __half2float(__float2half_rn(acc[mt][nt][0])) + bx;
            o0.y = __half2float(__float2half_rn(acc[mt][nt][1])) + by;
            o1.x = __half2float(__float2half_rn(acc[mt][nt][2])) + bx;
            o1.y = __half2float(__float2half_rn(acc[mt][nt][3])) + by;
            *reinterpret_cast<float2*>(out + (size_t)m * 8192 + n) = o0;
            *reinterpret_cast<float2*>(out + (size_t)(m + 8) * 8192 + n) = o1;
        }
    }
}

// ===========================================================================
// Host: bind inputs BY ELEMENT COUNT (all distinct) — immune to ordering.
//   x 1048576 | qweight 8388608 | scales 524288 | qzeros 65536 | bias 8192
// ===========================================================================
extern "C" void kernel_launch(void* const* d_in, const int* in_sizes, int n_in,
                              void* d_out, int out_size) {
    const void* x_raw = nullptr;
    const int* qweight = nullptr;
    const void* scales_raw = nullptr;
    const int* qzeros = nullptr;
    const float* bias = nullptr;

    for (int i = 0; i < n_in; i++) {
        switch (in_sizes[i]) {
            case X_ELEMS:     x_raw      = d_in[i];               break;
            case 8388608:     qweight    = (const int*)d_in[i];   break;
            case SCALE_ELEMS: scales_raw = d_in[i];               break;
            case 65536:       qzeros     = (const int*)d_in[i];   break;
            case 8192:        bias       = (const float*)d_in[i]; break;
            default: break;
        }
    }

    float* out = (float*)d_out;

    __half* gx = nullptr;
    __half* gs = nullptr;
    cudaGetSymbolAddress((void**)&gx, g_x);
    cudaGetSymbolAddress((void**)&gs, g_scales);

    detect_dtype_kernel<<<1, 32>>>((const uint32_t*)scales_raw);
    convert_kernel<<<256, 256>>>(x_raw, gx, X_ELEMS);
    convert_kernel<<<64, 256>>>(scales_raw, gs, SCALE_ELEMS);

    cudaFuncSetAttribute(awq_kernel, cudaFuncAttributeMaxDynamicSharedMemorySize, SMEM_TOTAL);
    awq_kernel<<<8192 / N_TILE, THREADS, SMEM_TOTAL>>>(qweight, qzeros, bias, out);
}